// round 2
// baseline (speedup 1.0000x reference)
#include <cuda_runtime.h>

#define N_PATIENT 50000
#define N_GENE    20000
#define N_EDGE    640000
#define P_DIM 64
#define G_DIM 32
#define H     128
#define OUT   8
#define TILE  64
#define NT    256

// Scratch (no cudaMalloc allowed): ~87 MB of __device__ globals.
__device__ float d_g  [N_GENE    * H];
__device__ float d_agg[N_PATIENT * H];
__device__ float d_p  [N_PATIENT * H];
__device__ float d_t  [N_PATIENT * H];

// ---------------------------------------------------------------- zero agg
__global__ void __launch_bounds__(NT) zero_kernel() {
    int i = blockIdx.x * blockDim.x + threadIdx.x;
    const int n4 = N_PATIENT * H / 4;
    if (i < n4) ((float4*)d_agg)[i] = make_float4(0.f, 0.f, 0.f, 0.f);
}

// ---------------------------------------------------------------- fused 2-layer MLP
// Y = relu(X @ W1 + b1) @ W2 + b2   (X: [nrows,K], Y: [nrows,H])
template<int K>
__device__ __forceinline__ void mlp2_body(
    float* sm,
    const float* __restrict__ X,
    const float* __restrict__ W1, const float* __restrict__ b1,
    const float* __restrict__ W2, const float* __restrict__ b2,
    float* __restrict__ Y, int nrows)
{
    float* sW1 = sm;                 // K*H
    float* sW2 = sW1 + K * H;        // H*H
    float* sb1 = sW2 + H * H;        // H
    float* sb2 = sb1 + H;            // H
    float* sA  = sb2 + H;            // TILE*K
    float* sH  = sA + TILE * K;      // TILE*H

    const int t = threadIdx.x;
    for (int i = t; i < K * H; i += NT) sW1[i] = W1[i];
    for (int i = t; i < H * H; i += NT) sW2[i] = W2[i];
    if (t < H) { sb1[t] = b1[t]; sb2[t] = b2[t]; }

    const int row0 = blockIdx.x * TILE;
    for (int i = t; i < TILE * K / 4; i += NT) {
        int r = (i * 4) / K, k = (i * 4) % K;
        int gr = row0 + r;
        float4 v = make_float4(0.f, 0.f, 0.f, 0.f);
        if (gr < nrows) v = *(const float4*)&X[gr * K + k];
        *(float4*)&sA[r * K + k] = v;
    }
    __syncthreads();

    const int c0 = (t & 15) * 8;       // 8 output cols
    const int rg = (t >> 4) * 4;       // 4 rows

    float acc[4][8];
    // ---- layer 1: H = relu(A @ W1 + b1)
    #pragma unroll
    for (int i = 0; i < 4; i++)
        #pragma unroll
        for (int j = 0; j < 8; j++) acc[i][j] = sb1[c0 + j];

    #pragma unroll 4
    for (int k = 0; k < K; k++) {
        float4 w0 = *(float4*)&sW1[k * H + c0];
        float4 w1 = *(float4*)&sW1[k * H + c0 + 4];
        #pragma unroll
        for (int i = 0; i < 4; i++) {
            float a = sA[(rg + i) * K + k];
            acc[i][0] += a * w0.x; acc[i][1] += a * w0.y;
            acc[i][2] += a * w0.z; acc[i][3] += a * w0.w;
            acc[i][4] += a * w1.x; acc[i][5] += a * w1.y;
            acc[i][6] += a * w1.z; acc[i][7] += a * w1.w;
        }
    }
    #pragma unroll
    for (int i = 0; i < 4; i++)
        #pragma unroll
        for (int j = 0; j < 8; j++)
            sH[(rg + i) * H + c0 + j] = fmaxf(acc[i][j], 0.f);
    __syncthreads();

    // ---- layer 2: Y = H @ W2 + b2
    #pragma unroll
    for (int i = 0; i < 4; i++)
        #pragma unroll
        for (int j = 0; j < 8; j++) acc[i][j] = sb2[c0 + j];

    #pragma unroll 4
    for (int k = 0; k < H; k++) {
        float4 w0 = *(float4*)&sW2[k * H + c0];
        float4 w1 = *(float4*)&sW2[k * H + c0 + 4];
        #pragma unroll
        for (int i = 0; i < 4; i++) {
            float a = sH[(rg + i) * H + k];
            acc[i][0] += a * w0.x; acc[i][1] += a * w0.y;
            acc[i][2] += a * w0.z; acc[i][3] += a * w0.w;
            acc[i][4] += a * w1.x; acc[i][5] += a * w1.y;
            acc[i][6] += a * w1.z; acc[i][7] += a * w1.w;
        }
    }
    #pragma unroll
    for (int i = 0; i < 4; i++) {
        int gr = row0 + rg + i;
        if (gr < nrows) {
            float4 o0 = make_float4(acc[i][0], acc[i][1], acc[i][2], acc[i][3]);
            float4 o1 = make_float4(acc[i][4], acc[i][5], acc[i][6], acc[i][7]);
            *(float4*)&Y[gr * H + c0]     = o0;
            *(float4*)&Y[gr * H + c0 + 4] = o1;
        }
    }
}

__global__ void __launch_bounds__(NT) gene_kernel(
    const float* X, const float* W1, const float* b1,
    const float* W2, const float* b2)
{
    extern __shared__ float sm[];
    mlp2_body<G_DIM>(sm, X, W1, b1, W2, b2, d_g, N_GENE);
}

__global__ void __launch_bounds__(NT) patient_kernel(
    const float* X, const float* W1, const float* b1,
    const float* W2, const float* b2)
{
    extern __shared__ float sm[];
    mlp2_body<P_DIM>(sm, X, W1, b1, W2, b2, d_p, N_PATIENT);
}

// ---------------------------------------------------------------- edge scatter
// one warp per edge: agg[dst] += g[src]  (vector red, 4 floats/lane)
__global__ void __launch_bounds__(NT) scatter_kernel(const int* __restrict__ edges) {
    int gtid = blockIdx.x * blockDim.x + threadIdx.x;
    int e = gtid >> 5;
    if (e >= N_EDGE) return;
    int lane = threadIdx.x & 31;
    int src = edges[e];
    int dst = edges[N_EDGE + e];
    float4 v = *(const float4*)&d_g[src * H + lane * 4];
    float* p = &d_agg[dst * H + lane * 4];
    asm volatile("red.global.add.v4.f32 [%0], {%1,%2,%3,%4};"
                 :: "l"(p), "f"(v.x), "f"(v.y), "f"(v.z), "f"(v.w)
                 : "memory");
}

// ---------------------------------------------------------------- SAGE layer
// T = relu(AG @ Wl + bl + PIN @ Wr); if FC: Y = T @ Wfc + bfc else Y = T
template<bool FC>
__device__ __forceinline__ void sage_body(
    float* sm,
    const float* __restrict__ AG, const float* __restrict__ PIN,
    const float* __restrict__ Wl, const float* __restrict__ bl,
    const float* __restrict__ Wr,
    const float* __restrict__ Wfc, const float* __restrict__ bfc,
    float* __restrict__ Y, int nrows)
{
    float* sWl  = sm;                  // H*H
    float* sWr  = sWl + H * H;         // H*H
    float* sbl  = sWr + H * H;         // H
    float* sAg  = sbl + H;             // TILE*H  (reused as p2 tile in FC path)
    float* sPin = sAg + TILE * H;      // TILE*H
    float* sWfc = sPin + TILE * H;     // H*OUT (FC only)
    float* sbfc = sWfc + H * OUT;      // OUT

    const int t = threadIdx.x;
    for (int i = t; i < H * H; i += NT) { sWl[i] = Wl[i]; sWr[i] = Wr[i]; }
    if (t < H) sbl[t] = bl[t];
    if (FC) {
        for (int i = t; i < H * OUT; i += NT) sWfc[i] = Wfc[i];
        if (t < OUT) sbfc[t] = bfc[t];
    }

    const int row0 = blockIdx.x * TILE;
    for (int i = t; i < TILE * H / 4; i += NT) {
        int r = (i * 4) / H, k = (i * 4) % H;
        int gr = row0 + r;
        float4 a = make_float4(0.f, 0.f, 0.f, 0.f), p = a;
        if (gr < nrows) {
            a = *(const float4*)&AG [gr * H + k];
            p = *(const float4*)&PIN[gr * H + k];
        }
        *(float4*)&sAg [r * H + k] = a;
        *(float4*)&sPin[r * H + k] = p;
    }
    __syncthreads();

    const int c0 = (t & 15) * 8;
    const int rg = (t >> 4) * 4;

    float acc[4][8];
    #pragma unroll
    for (int i = 0; i < 4; i++)
        #pragma unroll
        for (int j = 0; j < 8; j++) acc[i][j] = sbl[c0 + j];

    #pragma unroll 2
    for (int k = 0; k < H; k++) {
        float4 w0 = *(float4*)&sWl[k * H + c0];
        float4 w1 = *(float4*)&sWl[k * H + c0 + 4];
        float4 v0 = *(float4*)&sWr[k * H + c0];
        float4 v1 = *(float4*)&sWr[k * H + c0 + 4];
        #pragma unroll
        for (int i = 0; i < 4; i++) {
            float a = sAg [(rg + i) * H + k];
            float b = sPin[(rg + i) * H + k];
            acc[i][0] += a * w0.x; acc[i][1] += a * w0.y;
            acc[i][2] += a * w0.z; acc[i][3] += a * w0.w;
            acc[i][4] += a * w1.x; acc[i][5] += a * w1.y;
            acc[i][6] += a * w1.z; acc[i][7] += a * w1.w;
            acc[i][0] += b * v0.x; acc[i][1] += b * v0.y;
            acc[i][2] += b * v0.z; acc[i][3] += b * v0.w;
            acc[i][4] += b * v1.x; acc[i][5] += b * v1.y;
            acc[i][6] += b * v1.z; acc[i][7] += b * v1.w;
        }
    }

    if (!FC) {
        #pragma unroll
        for (int i = 0; i < 4; i++) {
            int gr = row0 + rg + i;
            if (gr < nrows) {
                #pragma unroll
                for (int j = 0; j < 8; j++)
                    Y[gr * H + c0 + j] = fmaxf(acc[i][j], 0.f);
            }
        }
    } else {
        __syncthreads();  // all k-loop reads of sAg done before overwrite
        #pragma unroll
        for (int i = 0; i < 4; i++)
            #pragma unroll
            for (int j = 0; j < 8; j++)
                sAg[(rg + i) * H + c0 + j] = fmaxf(acc[i][j], 0.f);
        __syncthreads();
        // FC: out[r][o] = sum_c p2[r][c] * Wfc[c][o] + bfc[o]
        #pragma unroll
        for (int u = 0; u < 2; u++) {
            int r = (t >> 3) + 32 * u;
            int o = t & 7;
            float s = sbfc[o];
            #pragma unroll 4
            for (int c = 0; c < H; c++)
                s += sAg[r * H + c] * sWfc[c * OUT + o];
            int gr = row0 + r;
            if (gr < nrows) Y[gr * OUT + o] = s;
        }
    }
}

__global__ void __launch_bounds__(NT) sage1_kernel(
    const float* Wl, const float* bl, const float* Wr)
{
    extern __shared__ float sm[];
    sage_body<false>(sm, d_agg, d_p, Wl, bl, Wr, nullptr, nullptr, d_t, N_PATIENT);
}

__global__ void __launch_bounds__(NT) sage2_kernel(
    const float* Wl, const float* bl, const float* Wr,
    const float* Wfc, const float* bfc, float* Y)
{
    extern __shared__ float sm[];
    sage_body<true>(sm, d_agg, d_t, Wl, bl, Wr, Wfc, bfc, Y, N_PATIENT);
}

// ---------------------------------------------------------------- launch
extern "C" void kernel_launch(void* const* d_in, const int* in_sizes, int n_in,
                              void* d_out, int out_size)
{
    const float* x_p  = (const float*)d_in[0];
    const float* x_g  = (const float*)d_in[1];
    const int*   eidx = (const int*)  d_in[2];
    const float* W_p1 = (const float*)d_in[3];
    const float* b_p1 = (const float*)d_in[4];
    const float* W_p2 = (const float*)d_in[5];
    const float* b_p2 = (const float*)d_in[6];
    const float* W_g1 = (const float*)d_in[7];
    const float* b_g1 = (const float*)d_in[8];
    const float* W_g2 = (const float*)d_in[9];
    const float* b_g2 = (const float*)d_in[10];
    const float* W1_l = (const float*)d_in[11];
    const float* b1_l = (const float*)d_in[12];
    const float* W1_r = (const float*)d_in[13];
    const float* W2_l = (const float*)d_in[14];
    const float* b2_l = (const float*)d_in[15];
    const float* W2_r = (const float*)d_in[16];
    const float* W_fc = (const float*)d_in[17];
    const float* b_fc = (const float*)d_in[18];
    float* out = (float*)d_out;

    const int smem_gene    = (G_DIM * H + H * H + 2 * H + TILE * G_DIM + TILE * H) * 4;
    const int smem_patient = (P_DIM * H + H * H + 2 * H + TILE * P_DIM + TILE * H) * 4;
    const int smem_sage1   = (2 * H * H + H + 2 * TILE * H) * 4;
    const int smem_sage2   = smem_sage1 + (H * OUT + OUT) * 4;

    cudaFuncSetAttribute(gene_kernel,    cudaFuncAttributeMaxDynamicSharedMemorySize, smem_gene);
    cudaFuncSetAttribute(patient_kernel, cudaFuncAttributeMaxDynamicSharedMemorySize, smem_patient);
    cudaFuncSetAttribute(sage1_kernel,   cudaFuncAttributeMaxDynamicSharedMemorySize, smem_sage1);
    cudaFuncSetAttribute(sage2_kernel,   cudaFuncAttributeMaxDynamicSharedMemorySize, smem_sage2);

    const int zero_blocks    = (N_PATIENT * H / 4 + NT - 1) / NT;
    const int gene_blocks    = (N_GENE    + TILE - 1) / TILE;
    const int patient_blocks = (N_PATIENT + TILE - 1) / TILE;
    const int scatter_blocks = (N_EDGE * 32 + NT - 1) / NT;

    zero_kernel   <<<zero_blocks, NT>>>();
    gene_kernel   <<<gene_blocks, NT, smem_gene>>>(x_g, W_g1, b_g1, W_g2, b_g2);
    patient_kernel<<<patient_blocks, NT, smem_patient>>>(x_p, W_p1, b_p1, W_p2, b_p2);
    scatter_kernel<<<scatter_blocks, NT>>>(eidx);
    sage1_kernel  <<<patient_blocks, NT, smem_sage1>>>(W1_l, b1_l, W1_r);
    sage2_kernel  <<<patient_blocks, NT, smem_sage2>>>(W2_l, b2_l, W2_r, W_fc, b_fc, out);
}

// round 3
// speedup vs baseline: 1.0264x; 1.0264x over previous
#include <cuda_runtime.h>

#define N_PATIENT 50000
#define N_GENE    20000
#define N_EDGE    640000
#define P_DIM 64
#define G_DIM 32
#define H     128
#define OUT   8
#define TILE  64
#define NT    256

// Scratch (no cudaMalloc allowed): ~87 MB of __device__ globals.
__device__ float d_g  [N_GENE    * H];
__device__ float d_agg[N_PATIENT * H];
__device__ float d_p  [N_PATIENT * H];
__device__ float d_t  [N_PATIENT * H];

typedef unsigned long long u64;

// ---- packed f32x2 helpers (FFMA2 path; ptxas never emits this from C++) ----
__device__ __forceinline__ void fma2(u64& c, u64 a, u64 b) {
    asm("fma.rn.f32x2 %0,%1,%2,%0;" : "+l"(c) : "l"(a), "l"(b));
}
__device__ __forceinline__ u64 pack_dup(float a) {
    u64 r; asm("mov.b64 %0,{%1,%1};" : "=l"(r) : "f"(a)); return r;
}
__device__ __forceinline__ void f4cast(const float4& v, u64& x, u64& y) {
    asm("mov.b64 %0,{%2,%3};\n\tmov.b64 %1,{%4,%5};"
        : "=l"(x), "=l"(y)
        : "f"(v.x), "f"(v.y), "f"(v.z), "f"(v.w));
}
__device__ __forceinline__ float2 unpk(u64 v) {
    float2 r; asm("mov.b64 {%0,%1},%2;" : "=f"(r.x), "=f"(r.y) : "l"(v)); return r;
}

// ---------------------------------------------------------------- zero agg
__global__ void __launch_bounds__(NT) zero_kernel() {
    int i = blockIdx.x * blockDim.x + threadIdx.x;
    const int n4 = N_PATIENT * H / 4;
    if (i < n4) ((float4*)d_agg)[i] = make_float4(0.f, 0.f, 0.f, 0.f);
}

// ---------------------------------------------------------------- fused 2-layer MLP
// Y = relu(X @ W1 + b1) @ W2 + b2   (X: [nrows,K], Y: [nrows,H])
template<int K>
__device__ __forceinline__ void mlp2_body(
    float* sm,
    const float* __restrict__ X,
    const float* __restrict__ W1, const float* __restrict__ b1,
    const float* __restrict__ W2, const float* __restrict__ b2,
    float* __restrict__ Y, int nrows)
{
    float* sW1 = sm;                 // K*H
    float* sW2 = sW1 + K * H;        // H*H
    float* sb1 = sW2 + H * H;        // H
    float* sb2 = sb1 + H;            // H
    float* sA  = sb2 + H;            // TILE*K
    float* sH  = sA + TILE * K;      // TILE*H

    const int t = threadIdx.x;
    for (int i = t; i < K * H; i += NT) sW1[i] = W1[i];
    for (int i = t; i < H * H; i += NT) sW2[i] = W2[i];
    if (t < H) { sb1[t] = b1[t]; sb2[t] = b2[t]; }

    const int row0 = blockIdx.x * TILE;
    for (int i = t; i < TILE * K / 4; i += NT) {
        int r = (i * 4) / K, k = (i * 4) % K;
        int gr = row0 + r;
        float4 v = make_float4(0.f, 0.f, 0.f, 0.f);
        if (gr < nrows) v = *(const float4*)&X[gr * K + k];
        *(float4*)&sA[r * K + k] = v;
    }
    __syncthreads();

    const int c0 = (t & 15) * 8;       // 8 output cols (4 packed pairs)
    const int rg = (t >> 4) * 4;       // 4 rows

    u64 acc[4][4];
    // ---- layer 1: H = relu(A @ W1 + b1)
    {
        float4 bv0 = *(float4*)&sb1[c0];
        float4 bv1 = *(float4*)&sb1[c0 + 4];
        u64 B[4]; f4cast(bv0, B[0], B[1]); f4cast(bv1, B[2], B[3]);
        #pragma unroll
        for (int i = 0; i < 4; i++)
            #pragma unroll
            for (int j = 0; j < 4; j++) acc[i][j] = B[j];
    }

    #pragma unroll 4
    for (int k = 0; k < K; k++) {
        float4 w0 = *(float4*)&sW1[k * H + c0];
        float4 w1 = *(float4*)&sW1[k * H + c0 + 4];
        u64 W[4]; f4cast(w0, W[0], W[1]); f4cast(w1, W[2], W[3]);
        #pragma unroll
        for (int i = 0; i < 4; i++) {
            u64 aa = pack_dup(sA[(rg + i) * K + k]);
            fma2(acc[i][0], aa, W[0]); fma2(acc[i][1], aa, W[1]);
            fma2(acc[i][2], aa, W[2]); fma2(acc[i][3], aa, W[3]);
        }
    }
    #pragma unroll
    for (int i = 0; i < 4; i++)
        #pragma unroll
        for (int j = 0; j < 4; j++) {
            float2 p = unpk(acc[i][j]);
            sH[(rg + i) * H + c0 + 2 * j]     = fmaxf(p.x, 0.f);
            sH[(rg + i) * H + c0 + 2 * j + 1] = fmaxf(p.y, 0.f);
        }
    __syncthreads();

    // ---- layer 2: Y = H @ W2 + b2
    {
        float4 bv0 = *(float4*)&sb2[c0];
        float4 bv1 = *(float4*)&sb2[c0 + 4];
        u64 B[4]; f4cast(bv0, B[0], B[1]); f4cast(bv1, B[2], B[3]);
        #pragma unroll
        for (int i = 0; i < 4; i++)
            #pragma unroll
            for (int j = 0; j < 4; j++) acc[i][j] = B[j];
    }

    #pragma unroll 4
    for (int k = 0; k < H; k++) {
        float4 w0 = *(float4*)&sW2[k * H + c0];
        float4 w1 = *(float4*)&sW2[k * H + c0 + 4];
        u64 W[4]; f4cast(w0, W[0], W[1]); f4cast(w1, W[2], W[3]);
        #pragma unroll
        for (int i = 0; i < 4; i++) {
            u64 aa = pack_dup(sH[(rg + i) * H + k]);
            fma2(acc[i][0], aa, W[0]); fma2(acc[i][1], aa, W[1]);
            fma2(acc[i][2], aa, W[2]); fma2(acc[i][3], aa, W[3]);
        }
    }
    #pragma unroll
    for (int i = 0; i < 4; i++) {
        int gr = row0 + rg + i;
        if (gr < nrows) {
            float2 p0 = unpk(acc[i][0]), p1 = unpk(acc[i][1]);
            float2 p2 = unpk(acc[i][2]), p3 = unpk(acc[i][3]);
            *(float4*)&Y[gr * H + c0]     = make_float4(p0.x, p0.y, p1.x, p1.y);
            *(float4*)&Y[gr * H + c0 + 4] = make_float4(p2.x, p2.y, p3.x, p3.y);
        }
    }
}

__global__ void __launch_bounds__(NT) gene_kernel(
    const float* X, const float* W1, const float* b1,
    const float* W2, const float* b2)
{
    extern __shared__ float sm[];
    mlp2_body<G_DIM>(sm, X, W1, b1, W2, b2, d_g, N_GENE);
}

__global__ void __launch_bounds__(NT) patient_kernel(
    const float* X, const float* W1, const float* b1,
    const float* W2, const float* b2)
{
    extern __shared__ float sm[];
    mlp2_body<P_DIM>(sm, X, W1, b1, W2, b2, d_p, N_PATIENT);
}

// ---------------------------------------------------------------- edge scatter
// one warp per edge: agg[dst] += g[src]  (vector red, 4 floats/lane)
__global__ void __launch_bounds__(NT) scatter_kernel(const int* __restrict__ edges) {
    int gtid = blockIdx.x * blockDim.x + threadIdx.x;
    int e = gtid >> 5;
    if (e >= N_EDGE) return;
    int lane = threadIdx.x & 31;
    int src = edges[e];
    int dst = edges[N_EDGE + e];
    float4 v = *(const float4*)&d_g[src * H + lane * 4];
    float* p = &d_agg[dst * H + lane * 4];
    asm volatile("red.global.add.v4.f32 [%0], {%1,%2,%3,%4};"
                 :: "l"(p), "f"(v.x), "f"(v.y), "f"(v.z), "f"(v.w)
                 : "memory");
}

// ---------------------------------------------------------------- SAGE layer
// T = relu(AG @ Wl + bl + PIN @ Wr); if FC: Y = T @ Wfc + bfc else Y = T
template<bool FC>
__device__ __forceinline__ void sage_body(
    float* sm,
    const float* __restrict__ AG, const float* __restrict__ PIN,
    const float* __restrict__ Wl, const float* __restrict__ bl,
    const float* __restrict__ Wr,
    const float* __restrict__ Wfc, const float* __restrict__ bfc,
    float* __restrict__ Y, int nrows)
{
    float* sWl  = sm;                  // H*H
    float* sWr  = sWl + H * H;         // H*H
    float* sbl  = sWr + H * H;         // H
    float* sAg  = sbl + H;             // TILE*H  (reused as p2 tile in FC path)
    float* sPin = sAg + TILE * H;      // TILE*H
    float* sWfc = sPin + TILE * H;     // H*OUT (FC only)
    float* sbfc = sWfc + H * OUT;      // OUT

    const int t = threadIdx.x;
    for (int i = t; i < H * H; i += NT) { sWl[i] = Wl[i]; sWr[i] = Wr[i]; }
    if (t < H) sbl[t] = bl[t];
    if (FC) {
        for (int i = t; i < H * OUT; i += NT) sWfc[i] = Wfc[i];
        if (t < OUT) sbfc[t] = bfc[t];
    }

    const int row0 = blockIdx.x * TILE;
    for (int i = t; i < TILE * H / 4; i += NT) {
        int r = (i * 4) / H, k = (i * 4) % H;
        int gr = row0 + r;
        float4 a = make_float4(0.f, 0.f, 0.f, 0.f), p = a;
        if (gr < nrows) {
            a = *(const float4*)&AG [gr * H + k];
            p = *(const float4*)&PIN[gr * H + k];
        }
        *(float4*)&sAg [r * H + k] = a;
        *(float4*)&sPin[r * H + k] = p;
    }
    __syncthreads();

    const int c0 = (t & 15) * 8;
    const int rg = (t >> 4) * 4;

    u64 acc[4][4];
    {
        float4 bv0 = *(float4*)&sbl[c0];
        float4 bv1 = *(float4*)&sbl[c0 + 4];
        u64 B[4]; f4cast(bv0, B[0], B[1]); f4cast(bv1, B[2], B[3]);
        #pragma unroll
        for (int i = 0; i < 4; i++)
            #pragma unroll
            for (int j = 0; j < 4; j++) acc[i][j] = B[j];
    }

    #pragma unroll 2
    for (int k = 0; k < H; k++) {
        float4 w0 = *(float4*)&sWl[k * H + c0];
        float4 w1 = *(float4*)&sWl[k * H + c0 + 4];
        float4 v0 = *(float4*)&sWr[k * H + c0];
        float4 v1 = *(float4*)&sWr[k * H + c0 + 4];
        u64 W[4], V[4];
        f4cast(w0, W[0], W[1]); f4cast(w1, W[2], W[3]);
        f4cast(v0, V[0], V[1]); f4cast(v1, V[2], V[3]);
        #pragma unroll
        for (int i = 0; i < 4; i++) {
            u64 aa = pack_dup(sAg [(rg + i) * H + k]);
            u64 bb = pack_dup(sPin[(rg + i) * H + k]);
            fma2(acc[i][0], aa, W[0]); fma2(acc[i][1], aa, W[1]);
            fma2(acc[i][2], aa, W[2]); fma2(acc[i][3], aa, W[3]);
            fma2(acc[i][0], bb, V[0]); fma2(acc[i][1], bb, V[1]);
            fma2(acc[i][2], bb, V[2]); fma2(acc[i][3], bb, V[3]);
        }
    }

    if (!FC) {
        #pragma unroll
        for (int i = 0; i < 4; i++) {
            int gr = row0 + rg + i;
            if (gr < nrows) {
                float2 p0 = unpk(acc[i][0]), p1 = unpk(acc[i][1]);
                float2 p2 = unpk(acc[i][2]), p3 = unpk(acc[i][3]);
                *(float4*)&Y[gr * H + c0] =
                    make_float4(fmaxf(p0.x, 0.f), fmaxf(p0.y, 0.f),
                                fmaxf(p1.x, 0.f), fmaxf(p1.y, 0.f));
                *(float4*)&Y[gr * H + c0 + 4] =
                    make_float4(fmaxf(p2.x, 0.f), fmaxf(p2.y, 0.f),
                                fmaxf(p3.x, 0.f), fmaxf(p3.y, 0.f));
            }
        }
    } else {
        __syncthreads();  // all k-loop reads of sAg done before overwrite
        #pragma unroll
        for (int i = 0; i < 4; i++) {
            #pragma unroll
            for (int j = 0; j < 4; j++) {
                float2 p = unpk(acc[i][j]);
                sAg[(rg + i) * H + c0 + 2 * j]     = fmaxf(p.x, 0.f);
                sAg[(rg + i) * H + c0 + 2 * j + 1] = fmaxf(p.y, 0.f);
            }
        }
        __syncthreads();
        // FC: out[r][o] = sum_c p2[r][c] * Wfc[c][o] + bfc[o]
        #pragma unroll
        for (int u = 0; u < 2; u++) {
            int r = (t >> 3) + 32 * u;
            int o = t & 7;
            float s = sbfc[o];
            #pragma unroll 4
            for (int c = 0; c < H; c++)
                s += sAg[r * H + c] * sWfc[c * OUT + o];
            int gr = row0 + r;
            if (gr < nrows) Y[gr * OUT + o] = s;
        }
    }
}

__global__ void __launch_bounds__(NT) sage1_kernel(
    const float* Wl, const float* bl, const float* Wr)
{
    extern __shared__ float sm[];
    sage_body<false>(sm, d_agg, d_p, Wl, bl, Wr, nullptr, nullptr, d_t, N_PATIENT);
}

__global__ void __launch_bounds__(NT) sage2_kernel(
    const float* Wl, const float* bl, const float* Wr,
    const float* Wfc, const float* bfc, float* Y)
{
    extern __shared__ float sm[];
    sage_body<true>(sm, d_agg, d_t, Wl, bl, Wr, Wfc, bfc, Y, N_PATIENT);
}

// ---------------------------------------------------------------- launch
extern "C" void kernel_launch(void* const* d_in, const int* in_sizes, int n_in,
                              void* d_out, int out_size)
{
    const float* x_p  = (const float*)d_in[0];
    const float* x_g  = (const float*)d_in[1];
    const int*   eidx = (const int*)  d_in[2];
    const float* W_p1 = (const float*)d_in[3];
    const float* b_p1 = (const float*)d_in[4];
    const float* W_p2 = (const float*)d_in[5];
    const float* b_p2 = (const float*)d_in[6];
    const float* W_g1 = (const float*)d_in[7];
    const float* b_g1 = (const float*)d_in[8];
    const float* W_g2 = (const float*)d_in[9];
    const float* b_g2 = (const float*)d_in[10];
    const float* W1_l = (const float*)d_in[11];
    const float* b1_l = (const float*)d_in[12];
    const float* W1_r = (const float*)d_in[13];
    const float* W2_l = (const float*)d_in[14];
    const float* b2_l = (const float*)d_in[15];
    const float* W2_r = (const float*)d_in[16];
    const float* W_fc = (const float*)d_in[17];
    const float* b_fc = (const float*)d_in[18];
    float* out = (float*)d_out;

    const int smem_gene    = (G_DIM * H + H * H + 2 * H + TILE * G_DIM + TILE * H) * 4;
    const int smem_patient = (P_DIM * H + H * H + 2 * H + TILE * P_DIM + TILE * H) * 4;
    const int smem_sage1   = (2 * H * H + H + 2 * TILE * H) * 4;
    const int smem_sage2   = smem_sage1 + (H * OUT + OUT) * 4;

    cudaFuncSetAttribute(gene_kernel,    cudaFuncAttributeMaxDynamicSharedMemorySize, smem_gene);
    cudaFuncSetAttribute(patient_kernel, cudaFuncAttributeMaxDynamicSharedMemorySize, smem_patient);
    cudaFuncSetAttribute(sage1_kernel,   cudaFuncAttributeMaxDynamicSharedMemorySize, smem_sage1);
    cudaFuncSetAttribute(sage2_kernel,   cudaFuncAttributeMaxDynamicSharedMemorySize, smem_sage2);

    const int zero_blocks    = (N_PATIENT * H / 4 + NT - 1) / NT;
    const int gene_blocks    = (N_GENE    + TILE - 1) / TILE;
    const int patient_blocks = (N_PATIENT + TILE - 1) / TILE;
    const int scatter_blocks = (N_EDGE * 32 + NT - 1) / NT;

    zero_kernel   <<<zero_blocks, NT>>>();
    gene_kernel   <<<gene_blocks, NT, smem_gene>>>(x_g, W_g1, b_g1, W_g2, b_g2);
    patient_kernel<<<patient_blocks, NT, smem_patient>>>(x_p, W_p1, b_p1, W_p2, b_p2);
    scatter_kernel<<<scatter_blocks, NT>>>(eidx);
    sage1_kernel  <<<patient_blocks, NT, smem_sage1>>>(W1_l, b1_l, W1_r);
    sage2_kernel  <<<patient_blocks, NT, smem_sage2>>>(W2_l, b2_l, W2_r, W_fc, b_fc, out);
}

// round 7
// speedup vs baseline: 1.3944x; 1.3585x over previous
#include <cuda_runtime.h>

#define N_PATIENT 50000
#define N_GENE    20000
#define N_EDGE    640000
#define P_DIM 64
#define G_DIM 32
#define H     128
#define OUT   8
#define TR    64      // rows per tile
#define TPAD  66      // padded row stride (floats) for transposed tiles
#define NT    256

typedef unsigned long long u64;

// Scratch (no cudaMalloc allowed)
__device__ float d_g  [N_GENE    * H];
__device__ float d_agg[N_PATIENT * H];
__device__ float d_p  [N_PATIENT * H];

// ---- packed f32x2 helpers ----
__device__ __forceinline__ void fma2(u64& c, u64 a, u64 b) {
    asm("fma.rn.f32x2 %0,%1,%2,%0;" : "+l"(c) : "l"(a), "l"(b));
}
__device__ __forceinline__ u64 dupf(float a) {
    u64 r; asm("mov.b64 %0,{%1,%1};" : "=l"(r) : "f"(a)); return r;
}
__device__ __forceinline__ float2 unpk(u64 v) {
    float2 r; asm("mov.b64 {%0,%1},%2;" : "=f"(r.x), "=f"(r.y) : "l"(v)); return r;
}

// ---------------------------------------------------------------- zero agg
__global__ void __launch_bounds__(NT) zero_kernel() {
    int i = blockIdx.x * blockDim.x + threadIdx.x;
    const int n4 = N_PATIENT * H / 4;
    if (i < n4) ((float4*)d_agg)[i] = make_float4(0.f, 0.f, 0.f, 0.f);
}

// ---------------------------------------------------------------- helpers
__device__ __forceinline__ void copyf4(float* dst, const float* __restrict__ src,
                                       int n, int t) {
    for (int i = t; i < n / 4; i += NT)
        ((float4*)dst)[i] = ((const float4*)src)[i];
}

// load TR rows x K cols of X into transposed padded tile XT[k][r]
template<int K>
__device__ __forceinline__ void load_T(float* XT, const float* __restrict__ X,
                                       int row0, int nrows, int t) {
    for (int i = t; i < TR * K / 4; i += NT) {
        int r = i % TR, kq = i / TR;     // lanes get consecutive r -> conflict-free STS
        int gr = row0 + r;
        float4 v = make_float4(0.f, 0.f, 0.f, 0.f);
        if (gr < nrows) v = *(const float4*)&X[gr * K + kq * 4];
        XT[(4 * kq + 0) * TPAD + r] = v.x;
        XT[(4 * kq + 1) * TPAD + r] = v.y;
        XT[(4 * kq + 2) * TPAD + r] = v.z;
        XT[(4 * kq + 3) * TPAD + r] = v.w;
    }
}

// acc[r][j] covers rows {2*lane+r}, cols {c0+2j, c0+2j+1}
__device__ __forceinline__ void init_bias(u64 acc[2][8], const float* sb, int c0) {
    const ulonglong2* b = (const ulonglong2*)&sb[c0];
    ulonglong2 b0 = b[0], b1 = b[1], b2 = b[2], b3 = b[3];
    u64 B[8] = {b0.x, b0.y, b1.x, b1.y, b2.x, b2.y, b3.x, b3.y};
    #pragma unroll
    for (int r = 0; r < 2; r++)
        #pragma unroll
        for (int j = 0; j < 8; j++) acc[r][j] = B[j];
}

// warp GEMM: acc += AT^T @ Wa (+ BT^T @ Wb). AT/BT: [K][TPAD] transposed tiles,
// Wa/Wb: [K][H] row-major. Lane covers rows 2*lane..2*lane+1, cols c0..c0+15.
template<int K, bool DUAL>
__device__ __forceinline__ void wgemm(
    u64 acc[2][8],
    const float* __restrict__ AT, const float* __restrict__ BT,
    const float* __restrict__ Wa, const float* __restrict__ Wb,
    int c0, int lane)
{
    #pragma unroll 4
    for (int k = 0; k < K; k++) {
        const ulonglong2* wa = (const ulonglong2*)&Wa[k * H + c0];
        ulonglong2 w0 = wa[0], w1 = wa[1], w2 = wa[2], w3 = wa[3];
        float2 a = *(const float2*)&AT[k * TPAD + 2 * lane];
        u64 a0 = dupf(a.x), a1 = dupf(a.y);
        fma2(acc[0][0], a0, w0.x); fma2(acc[0][1], a0, w0.y);
        fma2(acc[0][2], a0, w1.x); fma2(acc[0][3], a0, w1.y);
        fma2(acc[0][4], a0, w2.x); fma2(acc[0][5], a0, w2.y);
        fma2(acc[0][6], a0, w3.x); fma2(acc[0][7], a0, w3.y);
        fma2(acc[1][0], a1, w0.x); fma2(acc[1][1], a1, w0.y);
        fma2(acc[1][2], a1, w1.x); fma2(acc[1][3], a1, w1.y);
        fma2(acc[1][4], a1, w2.x); fma2(acc[1][5], a1, w2.y);
        fma2(acc[1][6], a1, w3.x); fma2(acc[1][7], a1, w3.y);
        if (DUAL) {
            const ulonglong2* wb = (const ulonglong2*)&Wb[k * H + c0];
            ulonglong2 v0 = wb[0], v1 = wb[1], v2 = wb[2], v3 = wb[3];
            float2 b = *(const float2*)&BT[k * TPAD + 2 * lane];
            u64 b0 = dupf(b.x), b1 = dupf(b.y);
            fma2(acc[0][0], b0, v0.x); fma2(acc[0][1], b0, v0.y);
            fma2(acc[0][2], b0, v1.x); fma2(acc[0][3], b0, v1.y);
            fma2(acc[0][4], b0, v2.x); fma2(acc[0][5], b0, v2.y);
            fma2(acc[0][6], b0, v3.x); fma2(acc[0][7], b0, v3.y);
            fma2(acc[1][0], b1, v0.x); fma2(acc[1][1], b1, v0.y);
            fma2(acc[1][2], b1, v1.x); fma2(acc[1][3], b1, v1.y);
            fma2(acc[1][4], b1, v2.x); fma2(acc[1][5], b1, v2.y);
            fma2(acc[1][6], b1, v3.x); fma2(acc[1][7], b1, v3.y);
        }
    }
}

// relu(acc) -> transposed tile OT[c][r]
__device__ __forceinline__ void store_relu_T(const u64 acc[2][8], float* OT,
                                             int c0, int lane) {
    #pragma unroll
    for (int j = 0; j < 8; j++) {
        float2 p0 = unpk(acc[0][j]);   // row 2*lane,   cols c0+2j, c0+2j+1
        float2 p1 = unpk(acc[1][j]);   // row 2*lane+1
        *(float2*)&OT[(c0 + 2 * j)     * TPAD + 2 * lane] =
            make_float2(fmaxf(p0.x, 0.f), fmaxf(p1.x, 0.f));
        *(float2*)&OT[(c0 + 2 * j + 1) * TPAD + 2 * lane] =
            make_float2(fmaxf(p0.y, 0.f), fmaxf(p1.y, 0.f));
    }
}

// ---------------------------------------------------------------- fused 2-layer MLP
template<int K>
__device__ __forceinline__ void mlp2_body(
    float* sm, const float* __restrict__ X,
    const float* __restrict__ W1, const float* __restrict__ b1,
    const float* __restrict__ W2, const float* __restrict__ b2,
    float* __restrict__ Y, int nrows)
{
    float* sW1 = sm;                 // K*H
    float* sW2 = sW1 + K * H;        // H*H
    float* sb1 = sW2 + H * H;        // H
    float* sb2 = sb1 + H;            // H
    float* sXT = sb2 + H;            // K*TPAD
    float* sHT = sXT + K * TPAD;     // H*TPAD

    const int t = threadIdx.x, lane = t & 31, wid = t >> 5, c0 = wid * 16;
    copyf4(sW1, W1, K * H, t);
    copyf4(sW2, W2, H * H, t);
    if (t < H) { sb1[t] = b1[t]; sb2[t] = b2[t]; }
    const int row0 = blockIdx.x * TR;
    load_T<K>(sXT, X, row0, nrows, t);
    __syncthreads();

    u64 acc[2][8];
    init_bias(acc, sb1, c0);
    wgemm<K, false>(acc, sXT, nullptr, sW1, nullptr, c0, lane);
    store_relu_T(acc, sHT, c0, lane);
    __syncthreads();

    init_bias(acc, sb2, c0);
    wgemm<H, false>(acc, sHT, nullptr, sW2, nullptr, c0, lane);

    #pragma unroll
    for (int r = 0; r < 2; r++) {
        int gr = row0 + 2 * lane + r;
        if (gr < nrows) {
            float2 p0 = unpk(acc[r][0]), p1 = unpk(acc[r][1]);
            float2 p2 = unpk(acc[r][2]), p3 = unpk(acc[r][3]);
            float2 p4 = unpk(acc[r][4]), p5 = unpk(acc[r][5]);
            float2 p6 = unpk(acc[r][6]), p7 = unpk(acc[r][7]);
            *(float4*)&Y[gr * H + c0]      = make_float4(p0.x, p0.y, p1.x, p1.y);
            *(float4*)&Y[gr * H + c0 + 4]  = make_float4(p2.x, p2.y, p3.x, p3.y);
            *(float4*)&Y[gr * H + c0 + 8]  = make_float4(p4.x, p4.y, p5.x, p5.y);
            *(float4*)&Y[gr * H + c0 + 12] = make_float4(p6.x, p6.y, p7.x, p7.y);
        }
    }
}

__global__ void __launch_bounds__(NT) gene_kernel(
    const float* X, const float* W1, const float* b1,
    const float* W2, const float* b2)
{
    extern __shared__ float sm[];
    mlp2_body<G_DIM>(sm, X, W1, b1, W2, b2, d_g, N_GENE);
}

__global__ void __launch_bounds__(NT) patient_kernel(
    const float* X, const float* W1, const float* b1,
    const float* W2, const float* b2)
{
    extern __shared__ float sm[];
    mlp2_body<P_DIM>(sm, X, W1, b1, W2, b2, d_p, N_PATIENT);
}

// ---------------------------------------------------------------- edge scatter
__global__ void __launch_bounds__(NT) scatter_kernel(const int* __restrict__ edges) {
    int gtid = blockIdx.x * blockDim.x + threadIdx.x;
    int e = gtid >> 5;
    if (e >= N_EDGE) return;
    int lane = threadIdx.x & 31;
    int src = edges[e];
    int dst = edges[N_EDGE + e];
    float4 v = *(const float4*)&d_g[src * H + lane * 4];
    float* p = &d_agg[dst * H + lane * 4];
    asm volatile("red.global.add.v4.f32 [%0], {%1,%2,%3,%4};"
                 :: "l"(p), "f"(v.x), "f"(v.y), "f"(v.z), "f"(v.w)
                 : "memory");
}

// ---------------------------------------------------------------- fused SAGE1+SAGE2+FC
__global__ void __launch_bounds__(NT) sage_fused_kernel(
    const float* W1l, const float* b1l, const float* W1r,
    const float* W2l, const float* b2l, const float* W2r,
    const float* Wfc, const float* bfc, float* out)
{
    extern __shared__ float sm[];
    float* sWa  = sm;                   // H*H
    float* sWb  = sWa + H * H;          // H*H
    float* sbl  = sWb + H * H;          // H
    float* sWfc = sbl + H;              // H*OUT
    float* sbfc = sWfc + H * OUT;       // OUT (pad to 16)
    float* sAgT = sbfc + 16;            // H*TPAD
    float* sXT  = sAgT + H * TPAD;      // H*TPAD (p, then t)

    const int t = threadIdx.x, lane = t & 31, wid = t >> 5, c0 = wid * 16;
    const int row0 = blockIdx.x * TR;

    copyf4(sWa, W1l, H * H, t);
    copyf4(sWb, W1r, H * H, t);
    if (t < H) sbl[t] = b1l[t];
    copyf4(sWfc, Wfc, H * OUT, t);
    if (t < OUT) sbfc[t] = bfc[t];
    load_T<H>(sAgT, d_agg, row0, N_PATIENT, t);
    load_T<H>(sXT,  d_p,   row0, N_PATIENT, t);
    __syncthreads();

    // layer 1: t = relu(agg@W1l + b1l + p@W1r)
    u64 acc[2][8];
    init_bias(acc, sbl, c0);
    wgemm<H, true>(acc, sAgT, sXT, sWa, sWb, c0, lane);
    __syncthreads();                       // all reads of sXT / sWa / sWb done
    store_relu_T(acc, sXT, c0, lane);      // t overwrites p tile
    copyf4(sWa, W2l, H * H, t);            // stream in layer-2 weights
    copyf4(sWb, W2r, H * H, t);
    if (t < H) sbl[t] = b2l[t];
    __syncthreads();

    // layer 2: p2 = relu(agg@W2l + b2l + t@W2r)
    init_bias(acc, sbl, c0);
    wgemm<H, true>(acc, sAgT, sXT, sWa, sWb, c0, lane);
    __syncthreads();                       // all reads of sAgT done
    store_relu_T(acc, sAgT, c0, lane);     // p2 overwrites agg tile
    __syncthreads();

    // FC: out[r][o] = bfc[o] + sum_c p2[r][c] * Wfc[c][o]
    int r = t & 63, og = t >> 6;           // og in 0..3 -> 2 output cols each
    float s0 = sbfc[2 * og], s1 = sbfc[2 * og + 1];
    #pragma unroll 4
    for (int c = 0; c < H; c++) {
        float pv = sAgT[c * TPAD + r];
        s0 += pv * sWfc[c * OUT + 2 * og];
        s1 += pv * sWfc[c * OUT + 2 * og + 1];
    }
    int gr = row0 + r;
    if (gr < N_PATIENT) {
        out[gr * OUT + 2 * og]     = s0;
        out[gr * OUT + 2 * og + 1] = s1;
    }
}

// ---------------------------------------------------------------- launch
extern "C" void kernel_launch(void* const* d_in, const int* in_sizes, int n_in,
                              void* d_out, int out_size)
{
    const float* x_p  = (const float*)d_in[0];
    const float* x_g  = (const float*)d_in[1];
    const int*   eidx = (const int*)  d_in[2];
    const float* W_p1 = (const float*)d_in[3];
    const float* b_p1 = (const float*)d_in[4];
    const float* W_p2 = (const float*)d_in[5];
    const float* b_p2 = (const float*)d_in[6];
    const float* W_g1 = (const float*)d_in[7];
    const float* b_g1 = (const float*)d_in[8];
    const float* W_g2 = (const float*)d_in[9];
    const float* b_g2 = (const float*)d_in[10];
    const float* W1_l = (const float*)d_in[11];
    const float* b1_l = (const float*)d_in[12];
    const float* W1_r = (const float*)d_in[13];
    const float* W2_l = (const float*)d_in[14];
    const float* b2_l = (const float*)d_in[15];
    const float* W2_r = (const float*)d_in[16];
    const float* W_fc = (const float*)d_in[17];
    const float* b_fc = (const float*)d_in[18];
    float* out = (float*)d_out;

    const int smem_gene    = (G_DIM * H + H * H + 2 * H + G_DIM * TPAD + H * TPAD) * 4;
    const int smem_patient = (P_DIM * H + H * H + 2 * H + P_DIM * TPAD + H * TPAD) * 4;
    const int smem_sage    = (2 * H * H + H + H * OUT + 16 + 2 * H * TPAD) * 4;

    cudaFuncSetAttribute(gene_kernel,       cudaFuncAttributeMaxDynamicSharedMemorySize, smem_gene);
    cudaFuncSetAttribute(patient_kernel,    cudaFuncAttributeMaxDynamicSharedMemorySize, smem_patient);
    cudaFuncSetAttribute(sage_fused_kernel, cudaFuncAttributeMaxDynamicSharedMemorySize, smem_sage);

    const int zero_blocks    = (N_PATIENT * H / 4 + NT - 1) / NT;
    const int gene_blocks    = (N_GENE    + TR - 1) / TR;
    const int patient_blocks = (N_PATIENT + TR - 1) / TR;
    const int scatter_blocks = (N_EDGE * 32 + NT - 1) / NT;

    zero_kernel      <<<zero_blocks, NT>>>();
    gene_kernel      <<<gene_blocks, NT, smem_gene>>>(x_g, W_g1, b_g1, W_g2, b_g2);
    patient_kernel   <<<patient_blocks, NT, smem_patient>>>(x_p, W_p1, b_p1, W_p2, b_p2);
    scatter_kernel   <<<scatter_blocks, NT>>>(eidx);
    sage_fused_kernel<<<patient_blocks, NT, smem_sage>>>(
        W1_l, b1_l, W1_r, W2_l, b2_l, W2_r, W_fc, b_fc, out);
}